// round 1
// baseline (speedup 1.0000x reference)
#include <cuda_runtime.h>
#include <cuda_bf16.h>

// Problem constants (validated against in_sizes at launch)
#define NN 50000
#define EE 800000
#define HH 128
#define GG 256

// ---------------- scratch (device globals: no allocation allowed) -----------
__device__ float g_zw[NN * HH];     // z @ W result
__device__ float g_z1[NN * HH];     // layer-1 activation
__device__ float g_dinv[NN];        // 1/sqrt(deg)
__device__ int   g_cnt[NN];         // histogram / fill cursor
__device__ int   g_rowptr[NN + 1];  // CSR row pointers (by dst)
__device__ int   g_col[EE];         // CSR column (src) indices

// ---------------- init: zero histogram + zero pool output -------------------
__global__ void init_kernel(float* __restrict__ g_pool, int n, int gsize) {
    int i = blockIdx.x * blockDim.x + threadIdx.x;
    if (i < n)     g_cnt[i] = 0;
    if (i < gsize) g_pool[i] = 0.0f;
}

// ---------------- degree histogram on dst ------------------------------------
__global__ void count_kernel(const int* __restrict__ dst, int e) {
    int i = blockIdx.x * blockDim.x + threadIdx.x;
    if (i < e) atomicAdd(&g_cnt[dst[i]], 1);
}

// ---------------- single-block exclusive scan + dinv + cnt reset -------------
__global__ void scan_kernel(int n) {
    __shared__ int warp_sums[32];
    int tid = threadIdx.x;
    int lane = tid & 31, wid = tid >> 5;
    int offset = 0;
    for (int base = 0; base < n; base += 1024) {
        int i = base + tid;
        int v = (i < n) ? g_cnt[i] : 0;
        int x = v;
        #pragma unroll
        for (int d = 1; d < 32; d <<= 1) {
            int y = __shfl_up_sync(0xFFFFFFFFu, x, d);
            if (lane >= d) x += y;
        }
        if (lane == 31) warp_sums[wid] = x;
        __syncthreads();
        if (wid == 0) {
            int w = warp_sums[lane];
            #pragma unroll
            for (int d = 1; d < 32; d <<= 1) {
                int y = __shfl_up_sync(0xFFFFFFFFu, w, d);
                if (lane >= d) w += y;
            }
            warp_sums[lane] = w;
        }
        __syncthreads();
        int incl = x + (wid > 0 ? warp_sums[wid - 1] : 0);
        if (i < n) {
            g_rowptr[i + 1] = offset + incl;
            g_dinv[i] = rsqrtf((float)(v + 1));  // +1 self loop
            g_cnt[i] = 0;                        // reset for fill pass
        }
        offset += warp_sums[31];
        __syncthreads();
    }
    if (tid == 0) g_rowptr[0] = 0;
}

// ---------------- CSR fill ----------------------------------------------------
__global__ void fill_kernel(const int* __restrict__ src,
                            const int* __restrict__ dst, int e) {
    int i = blockIdx.x * blockDim.x + threadIdx.x;
    if (i < e) {
        int d = dst[i];
        int pos = g_rowptr[d] + atomicAdd(&g_cnt[d], 1);
        g_col[pos] = src[i];
    }
}

// ---------------- SGEMM: C[n,128] = A[n,128] * W[128,128] --------------------
// Block: 256 threads, 128x128 tile, 8x8 per thread, BK=8.
__global__ void __launch_bounds__(256) gemm128_kernel(
    const float* __restrict__ A, const float* __restrict__ W,
    float* __restrict__ C, int n) {
    __shared__ float As[8][128];
    __shared__ float Bs[8][128];

    int tid = threadIdx.x;
    int m0 = blockIdx.x * 128;

    int arow = tid % 128;          // A-load: row within tile
    int akg  = tid / 128;          // which float4 of the 8-wide k chunk
    int brow = tid / 32;           // B-load: k within chunk
    int bcol = (tid % 32) * 4;

    int trow = (tid / 16) * 8;     // compute micro-tile
    int tcol = (tid % 16) * 8;

    float acc[8][8];
    #pragma unroll
    for (int i = 0; i < 8; i++)
        #pragma unroll
        for (int j = 0; j < 8; j++) acc[i][j] = 0.0f;

    int arow_g = m0 + arow;
    if (arow_g >= n) arow_g = n - 1;   // clamped (stores are guarded)

    for (int k0 = 0; k0 < 128; k0 += 8) {
        float4 a = *(const float4*)&A[(size_t)arow_g * 128 + k0 + akg * 4];
        float4 b = *(const float4*)&W[(size_t)(k0 + brow) * 128 + bcol];
        As[akg * 4 + 0][arow] = a.x;
        As[akg * 4 + 1][arow] = a.y;
        As[akg * 4 + 2][arow] = a.z;
        As[akg * 4 + 3][arow] = a.w;
        *(float4*)&Bs[brow][bcol] = b;
        __syncthreads();

        #pragma unroll
        for (int kk = 0; kk < 8; kk++) {
            float ar[8], br[8];
            *(float4*)&ar[0] = *(const float4*)&As[kk][trow];
            *(float4*)&ar[4] = *(const float4*)&As[kk][trow + 4];
            *(float4*)&br[0] = *(const float4*)&Bs[kk][tcol];
            *(float4*)&br[4] = *(const float4*)&Bs[kk][tcol + 4];
            #pragma unroll
            for (int i = 0; i < 8; i++)
                #pragma unroll
                for (int j = 0; j < 8; j++)
                    acc[i][j] = fmaf(ar[i], br[j], acc[i][j]);
        }
        __syncthreads();
    }

    #pragma unroll
    for (int i = 0; i < 8; i++) {
        int m = m0 + trow + i;
        if (m < n) {
            *(float4*)&C[(size_t)m * 128 + tcol]     = *(float4*)&acc[i][0];
            *(float4*)&C[(size_t)m * 128 + tcol + 4] = *(float4*)&acc[i][4];
        }
    }
}

// ---------------- gather + bias + PReLU + pool --------------------------------
// One warp per node. out[i] = prelu(dinv[i]*(dinv[i]*zw[i] + sum dinv[s]*zw[s]) + b)
__global__ void gather_kernel(const float* __restrict__ zw,
                              const float* __restrict__ bias,
                              const float* __restrict__ alpha,
                              const int* __restrict__ batch,
                              float* __restrict__ zout,
                              float* __restrict__ pool,  // g + layer col offset
                              int n) {
    int warp = (blockIdx.x * blockDim.x + threadIdx.x) >> 5;
    int lane = threadIdx.x & 31;
    if (warp >= n) return;
    int i = warp;

    const float4* zwv = (const float4*)zw;
    float di = g_dinv[i];
    float4 v = zwv[(size_t)i * 32 + lane];
    float4 acc;
    acc.x = di * v.x; acc.y = di * v.y; acc.z = di * v.z; acc.w = di * v.w;

    int e0 = g_rowptr[i], e1 = g_rowptr[i + 1];
    for (int e = e0; e < e1; e++) {
        int s = g_col[e];
        float ds = g_dinv[s];
        float4 u = zwv[(size_t)s * 32 + lane];
        acc.x = fmaf(ds, u.x, acc.x);
        acc.y = fmaf(ds, u.y, acc.y);
        acc.z = fmaf(ds, u.z, acc.z);
        acc.w = fmaf(ds, u.w, acc.w);
    }

    float4 b  = ((const float4*)bias)[lane];
    float4 al = ((const float4*)alpha)[lane];
    float z0 = fmaf(acc.x, di, b.x);
    float z1 = fmaf(acc.y, di, b.y);
    float z2 = fmaf(acc.z, di, b.z);
    float z3 = fmaf(acc.w, di, b.w);
    z0 = z0 > 0.0f ? z0 : al.x * z0;
    z1 = z1 > 0.0f ? z1 : al.y * z1;
    z2 = z2 > 0.0f ? z2 : al.z * z2;
    z3 = z3 > 0.0f ? z3 : al.w * z3;

    float4 out = {z0, z1, z2, z3};
    ((float4*)zout)[(size_t)i * 32 + lane] = out;

    int gi = batch[i];
    float* p = &pool[(size_t)gi * 256 + lane * 4];
    atomicAdd(p + 0, z0);
    atomicAdd(p + 1, z1);
    atomicAdd(p + 2, z2);
    atomicAdd(p + 3, z3);
}

// ---------------- launch -------------------------------------------------------
extern "C" void kernel_launch(void* const* d_in, const int* in_sizes, int n_in,
                              void* d_out, int out_size) {
    const float* x      = (const float*)d_in[0];
    const int*   eidx   = (const int*)d_in[1];
    const int*   batch  = (const int*)d_in[2];
    const float* W0     = (const float*)d_in[3];
    const float* b0     = (const float*)d_in[4];
    const float* alpha0 = (const float*)d_in[5];
    const float* W1     = (const float*)d_in[6];
    const float* b1     = (const float*)d_in[7];
    const float* alpha1 = (const float*)d_in[8];

    int n = in_sizes[0] / HH;      // 50000
    int e = in_sizes[1] / 2;       // 800000
    const int* src = eidx;
    const int* dst = eidx + e;

    float* z2_out = (float*)d_out;                 // [n,128]
    float* g_pool = (float*)d_out + (size_t)n * HH; // [G, 256]
    int gsize = out_size - n * HH;                  // 65536

    float* zw;  cudaGetSymbolAddress((void**)&zw, g_zw);
    float* z1;  cudaGetSymbolAddress((void**)&z1, g_z1);

    int initN = (n > gsize ? n : gsize);
    init_kernel<<<(initN + 255) / 256, 256>>>(g_pool, n, gsize);
    count_kernel<<<(e + 255) / 256, 256>>>(dst, e);
    scan_kernel<<<1, 1024>>>(n);
    fill_kernel<<<(e + 255) / 256, 256>>>(src, dst, e);

    int gemm_blocks = (n + 127) / 128;
    int gather_blocks = (n * 32 + 255) / 256;

    // Layer 0
    gemm128_kernel<<<gemm_blocks, 256>>>(x, W0, zw, n);
    gather_kernel<<<gather_blocks, 256>>>(zw, b0, alpha0, batch, z1, g_pool, n);
    // Layer 1
    gemm128_kernel<<<gemm_blocks, 256>>>(z1, W1, zw, n);
    gather_kernel<<<gather_blocks, 256>>>(zw, b1, alpha1, batch, z2_out,
                                          g_pool + HH, n);
}

// round 2
// speedup vs baseline: 1.3397x; 1.3397x over previous
#include <cuda_runtime.h>
#include <cuda_bf16.h>
#include <cstdint>

#define NN 50000
#define EE 800000
#define HH 128
#define GG 256
#define SCHUNK 512
#define MAXNB 128   // >= ceil(NN/SCHUNK)=98

// ---------------- scratch (device globals: no allocation allowed) -----------
__device__ float g_zw[NN * HH];     // z @ W result
__device__ float g_z1[NN * HH];     // layer-1 activation
__device__ float g_dinv[NN];        // 1/sqrt(deg)
__device__ int   g_cnt[NN];         // histogram / fill cursor
__device__ int   g_rowptr[NN + 1];  // CSR row pointers (by dst)
__device__ int   g_col[EE];         // CSR column (src) indices
__device__ int   g_bsum[MAXNB];     // per-chunk sums
__device__ int   g_boff[MAXNB];     // exclusive chunk offsets

// ---------------- init: zero histogram + zero pool output -------------------
__global__ void init_kernel(float* __restrict__ g_pool, int n, int gsize) {
    int i = blockIdx.x * blockDim.x + threadIdx.x;
    if (i < n)     g_cnt[i] = 0;
    if (i < gsize) g_pool[i] = 0.0f;
}

// ---------------- degree histogram on dst ------------------------------------
__global__ void count_kernel(const int* __restrict__ dst, int e) {
    int i = blockIdx.x * blockDim.x + threadIdx.x;
    if (i < e) atomicAdd(&g_cnt[dst[i]], 1);
}

// ---------------- scan phase 1: per-chunk reduce ------------------------------
__global__ void __launch_bounds__(256) reduce_kernel(int n) {
    __shared__ int ws[8];
    int b = blockIdx.x, tid = threadIdx.x;
    int lane = tid & 31, wid = tid >> 5;
    int i = b * SCHUNK + tid * 2;
    int s = (i < n ? g_cnt[i] : 0) + (i + 1 < n ? g_cnt[i + 1] : 0);
    #pragma unroll
    for (int d = 16; d > 0; d >>= 1) s += __shfl_down_sync(0xFFFFFFFFu, s, d);
    if (lane == 0) ws[wid] = s;
    __syncthreads();
    if (tid == 0) {
        int t = 0;
        #pragma unroll
        for (int w = 0; w < 8; w++) t += ws[w];
        g_bsum[b] = t;
    }
}

// ---------------- scan phase 2: scan the chunk sums (1 block) -----------------
__global__ void scan_bsums_kernel(int nb) {
    __shared__ int ws[4];
    int tid = threadIdx.x;              // 128 threads
    int lane = tid & 31, wid = tid >> 5;
    int v = tid < nb ? g_bsum[tid] : 0;
    int x = v;
    #pragma unroll
    for (int d = 1; d < 32; d <<= 1) {
        int y = __shfl_up_sync(0xFFFFFFFFu, x, d);
        if (lane >= d) x += y;
    }
    if (lane == 31) ws[wid] = x;
    __syncthreads();
    int add = 0;
    for (int w = 0; w < wid; w++) add += ws[w];
    if (tid < nb) g_boff[tid] = x - v + add;
}

// ---------------- scan phase 3: per-chunk scan + write rowptr/dinv ------------
__global__ void __launch_bounds__(256) scan_write_kernel(int n) {
    __shared__ int ws[8];
    int b = blockIdx.x, tid = threadIdx.x;
    int lane = tid & 31, wid = tid >> 5;
    int base = b * SCHUNK + tid * 2;
    int v0 = base < n ? g_cnt[base] : 0;
    int v1 = base + 1 < n ? g_cnt[base + 1] : 0;
    int t = v0 + v1;
    int x = t;
    #pragma unroll
    for (int d = 1; d < 32; d <<= 1) {
        int y = __shfl_up_sync(0xFFFFFFFFu, x, d);
        if (lane >= d) x += y;
    }
    if (lane == 31) ws[wid] = x;
    __syncthreads();
    int add = g_boff[b];
    for (int w = 0; w < wid; w++) add += ws[w];
    int excl = x - t + add;
    if (base < n) {
        g_rowptr[base + 1] = excl + v0;
        g_dinv[base] = rsqrtf((float)(v0 + 1));
        g_cnt[base] = 0;
    }
    if (base + 1 < n) {
        g_rowptr[base + 2] = excl + v0 + v1;
        g_dinv[base + 1] = rsqrtf((float)(v1 + 1));
        g_cnt[base + 1] = 0;
    }
    if (b == 0 && tid == 0) g_rowptr[0] = 0;
}

// ---------------- CSR fill ----------------------------------------------------
__global__ void fill_kernel(const int* __restrict__ src,
                            const int* __restrict__ dst, int e) {
    int i = blockIdx.x * blockDim.x + threadIdx.x;
    if (i < e) {
        int d = dst[i];
        int pos = g_rowptr[d] + atomicAdd(&g_cnt[d], 1);
        g_col[pos] = src[i];
    }
}

// ---------------- TF32 helpers -------------------------------------------------
__device__ __forceinline__ uint32_t f2tf32(float x) {
    uint32_t y;
    asm("cvt.rna.tf32.f32 %0, %1;" : "=r"(y) : "f"(x));
    return y;
}

__device__ __forceinline__ void mma_tf32(float c[4],
                                         uint32_t a0, uint32_t a1,
                                         uint32_t a2, uint32_t a3,
                                         uint32_t b0, uint32_t b1) {
    asm volatile(
        "mma.sync.aligned.m16n8k8.row.col.f32.tf32.tf32.f32 "
        "{%0,%1,%2,%3}, {%4,%5,%6,%7}, {%8,%9}, {%0,%1,%2,%3};"
        : "+f"(c[0]), "+f"(c[1]), "+f"(c[2]), "+f"(c[3])
        : "r"(a0), "r"(a1), "r"(a2), "r"(a3), "r"(b0), "r"(b1));
}

// ---------------- 3xTF32 GEMM: C[n,128] = A[n,128] * W[128,128] ---------------
// Block: 256 threads (8 warps), 128x128 output tile, K-chunks of 32.
// Warp tile: 32 rows x 64 cols; mma m16n8k8 (2 m-subtiles x 8 n-tiles).
__global__ void __launch_bounds__(256) gemm_tf32_kernel(
    const float* __restrict__ A, const float* __restrict__ W,
    float* __restrict__ C, int n) {
    __shared__ float As[128][36];   // pad 4: conflict-free A frag reads
    __shared__ float Bs[32][136];   // pad 8: conflict-free B frag reads

    int tid = threadIdx.x;
    int lane = tid & 31, wid = tid >> 5;
    int m0 = blockIdx.x * 128;
    int wm = wid >> 1;              // 0..3 : rows 32*wm
    int wn = wid & 1;               // 0..1 : cols 64*wn

    float acc[2][8][4];
    #pragma unroll
    for (int ms = 0; ms < 2; ms++)
        #pragma unroll
        for (int nt = 0; nt < 8; nt++)
            #pragma unroll
            for (int j = 0; j < 4; j++) acc[ms][nt][j] = 0.0f;

    int kq = lane & 3;     // k offset within 8-wide mma k
    int rq = lane >> 2;    // row/col offset within frag

    for (int k0 = 0; k0 < 128; k0 += 32) {
        // --- stage A tile [128 x 32] : 1024 float4, 4 per thread ---
        #pragma unroll
        for (int it = 0; it < 4; it++) {
            int f = tid + 256 * it;
            int row = f >> 3;
            int k4 = (f & 7) * 4;
            int rg = m0 + row;
            if (rg >= n) rg = n - 1;
            float4 a = *(const float4*)&A[(size_t)rg * 128 + k0 + k4];
            *(float4*)&As[row][k4] = a;
        }
        // --- stage B tile [32 x 128] ---
        #pragma unroll
        for (int it = 0; it < 4; it++) {
            int f = tid + 256 * it;
            int k = f >> 5;
            int nc = (f & 31) * 4;
            float4 b = *(const float4*)&W[(size_t)(k0 + k) * 128 + nc];
            *(float4*)&Bs[k][nc] = b;
        }
        __syncthreads();

        #pragma unroll
        for (int kk = 0; kk < 32; kk += 8) {
            #pragma unroll
            for (int ms = 0; ms < 2; ms++) {
                int r = wm * 32 + ms * 16 + rq;
                float af0 = As[r][kk + kq];
                float af1 = As[r + 8][kk + kq];
                float af2 = As[r][kk + kq + 4];
                float af3 = As[r + 8][kk + kq + 4];
                uint32_t ah0 = f2tf32(af0), ah1 = f2tf32(af1);
                uint32_t ah2 = f2tf32(af2), ah3 = f2tf32(af3);
                uint32_t al0 = f2tf32(af0 - __uint_as_float(ah0));
                uint32_t al1 = f2tf32(af1 - __uint_as_float(ah1));
                uint32_t al2 = f2tf32(af2 - __uint_as_float(ah2));
                uint32_t al3 = f2tf32(af3 - __uint_as_float(ah3));
                #pragma unroll
                for (int nt = 0; nt < 8; nt++) {
                    int nc = wn * 64 + nt * 8 + rq;
                    float bf0 = Bs[kk + kq][nc];
                    float bf1 = Bs[kk + kq + 4][nc];
                    uint32_t bh0 = f2tf32(bf0), bh1 = f2tf32(bf1);
                    uint32_t bl0 = f2tf32(bf0 - __uint_as_float(bh0));
                    uint32_t bl1 = f2tf32(bf1 - __uint_as_float(bh1));
                    mma_tf32(acc[ms][nt], al0, al1, al2, al3, bh0, bh1);
                    mma_tf32(acc[ms][nt], ah0, ah1, ah2, ah3, bl0, bl1);
                    mma_tf32(acc[ms][nt], ah0, ah1, ah2, ah3, bh0, bh1);
                }
            }
        }
        __syncthreads();
    }

    // --- epilogue ---
    #pragma unroll
    for (int ms = 0; ms < 2; ms++) {
        int r0 = m0 + wm * 32 + ms * 16 + rq;
        #pragma unroll
        for (int nt = 0; nt < 8; nt++) {
            int nc = wn * 64 + nt * 8 + (lane & 3) * 2;
            if (r0 < n) {
                float2 v = {acc[ms][nt][0], acc[ms][nt][1]};
                *(float2*)&C[(size_t)r0 * 128 + nc] = v;
            }
            if (r0 + 8 < n) {
                float2 v = {acc[ms][nt][2], acc[ms][nt][3]};
                *(float2*)&C[(size_t)(r0 + 8) * 128 + nc] = v;
            }
        }
    }
}

// ---------------- gather + bias + PReLU + pool --------------------------------
__global__ void gather_kernel(const float* __restrict__ zw,
                              const float* __restrict__ bias,
                              const float* __restrict__ alpha,
                              const int* __restrict__ batch,
                              float* __restrict__ zout,
                              float* __restrict__ pool,
                              int n) {
    int warp = (blockIdx.x * blockDim.x + threadIdx.x) >> 5;
    int lane = threadIdx.x & 31;
    if (warp >= n) return;
    int i = warp;

    const float4* zwv = (const float4*)zw;
    float di = g_dinv[i];
    float4 v = zwv[(size_t)i * 32 + lane];
    float4 acc;
    acc.x = di * v.x; acc.y = di * v.y; acc.z = di * v.z; acc.w = di * v.w;

    int e0 = g_rowptr[i], e1 = g_rowptr[i + 1];
    for (int e = e0; e < e1; e++) {
        int s = g_col[e];
        float ds = g_dinv[s];
        float4 u = zwv[(size_t)s * 32 + lane];
        acc.x = fmaf(ds, u.x, acc.x);
        acc.y = fmaf(ds, u.y, acc.y);
        acc.z = fmaf(ds, u.z, acc.z);
        acc.w = fmaf(ds, u.w, acc.w);
    }

    float4 b  = ((const float4*)bias)[lane];
    float4 al = ((const float4*)alpha)[lane];
    float z0 = fmaf(acc.x, di, b.x);
    float z1 = fmaf(acc.y, di, b.y);
    float z2 = fmaf(acc.z, di, b.z);
    float z3 = fmaf(acc.w, di, b.w);
    z0 = z0 > 0.0f ? z0 : al.x * z0;
    z1 = z1 > 0.0f ? z1 : al.y * z1;
    z2 = z2 > 0.0f ? z2 : al.z * z2;
    z3 = z3 > 0.0f ? z3 : al.w * z3;

    float4 out = {z0, z1, z2, z3};
    ((float4*)zout)[(size_t)i * 32 + lane] = out;

    int gi = batch[i];
    float* p = &pool[(size_t)gi * 256 + lane * 4];
    atomicAdd(p + 0, z0);
    atomicAdd(p + 1, z1);
    atomicAdd(p + 2, z2);
    atomicAdd(p + 3, z3);
}

// ---------------- launch -------------------------------------------------------
extern "C" void kernel_launch(void* const* d_in, const int* in_sizes, int n_in,
                              void* d_out, int out_size) {
    const float* x      = (const float*)d_in[0];
    const int*   eidx   = (const int*)d_in[1];
    const int*   batch  = (const int*)d_in[2];
    const float* W0     = (const float*)d_in[3];
    const float* b0     = (const float*)d_in[4];
    const float* alpha0 = (const float*)d_in[5];
    const float* W1     = (const float*)d_in[6];
    const float* b1     = (const float*)d_in[7];
    const float* alpha1 = (const float*)d_in[8];

    int n = in_sizes[0] / HH;       // 50000
    int e = in_sizes[1] / 2;        // 800000
    const int* src = eidx;
    const int* dst = eidx + e;

    float* z2_out = (float*)d_out;                   // [n,128]
    float* g_pool = (float*)d_out + (size_t)n * HH;  // [G, 256]
    int gsize = out_size - n * HH;                   // 65536

    float* zw;  cudaGetSymbolAddress((void**)&zw, g_zw);
    float* z1;  cudaGetSymbolAddress((void**)&z1, g_z1);

    int nb = (n + SCHUNK - 1) / SCHUNK;

    int initN = (n > gsize ? n : gsize);
    init_kernel<<<(initN + 255) / 256, 256>>>(g_pool, n, gsize);
    count_kernel<<<(e + 255) / 256, 256>>>(dst, e);
    reduce_kernel<<<nb, 256>>>(n);
    scan_bsums_kernel<<<1, 128>>>(nb);
    scan_write_kernel<<<nb, 256>>>(n);
    fill_kernel<<<(e + 255) / 256, 256>>>(src, dst, e);

    int gemm_blocks = (n + 127) / 128;
    int gather_blocks = (n * 32 + 255) / 256;

    // Layer 0
    gemm_tf32_kernel<<<gemm_blocks, 256>>>(x, W0, zw, n);
    gather_kernel<<<gather_blocks, 256>>>(zw, b0, alpha0, batch, z1, g_pool, n);
    // Layer 1
    gemm_tf32_kernel<<<gemm_blocks, 256>>>(z1, W1, zw, n);
    gather_kernel<<<gather_blocks, 256>>>(zw, b1, alpha1, batch, z2_out,
                                          g_pool + HH, n);
}

// round 3
// speedup vs baseline: 1.5211x; 1.1354x over previous
#include <cuda_runtime.h>
#include <cuda_bf16.h>
#include <cstdint>

#define NN 50000
#define EE 800000
#define HH 128
#define GG 256
#define SCHUNK 512
#define MAXNB 128   // >= ceil(NN/SCHUNK)=98

// ---------------- scratch (device globals: no allocation allowed) -----------
__device__ float g_zw[NN * HH];     // z @ W result
__device__ float g_z1[NN * HH];     // layer-1 activation
__device__ float g_dinv[NN];        // 1/sqrt(deg)
__device__ int   g_cnt[NN];         // degree histogram (INVARIANT: 0 at launch entry)
__device__ int   g_cur[NN];         // fill cursor (= rowptr at fill start)
__device__ int   g_rowptr[NN + 1];  // CSR row pointers (by dst)
__device__ int   g_col[EE];         // CSR column (src) indices
__device__ int   g_bsum[MAXNB];     // per-chunk sums
__device__ int   g_boff[MAXNB];     // exclusive chunk offsets

// ---------------- TF32 helpers -------------------------------------------------
__device__ __forceinline__ uint32_t f2tf32(float x) {
    uint32_t y;
    asm("cvt.rna.tf32.f32 %0, %1;" : "=r"(y) : "f"(x));
    return y;
}

__device__ __forceinline__ void mma_tf32(float c[4],
                                         uint32_t a0, uint32_t a1,
                                         uint32_t a2, uint32_t a3,
                                         uint32_t b0, uint32_t b1) {
    asm volatile(
        "mma.sync.aligned.m16n8k8.row.col.f32.tf32.tf32.f32 "
        "{%0,%1,%2,%3}, {%4,%5,%6,%7}, {%8,%9}, {%0,%1,%2,%3};"
        : "+f"(c[0]), "+f"(c[1]), "+f"(c[2]), "+f"(c[3])
        : "r"(a0), "r"(a1), "r"(a2), "r"(a3), "r"(b0), "r"(b1));
}

// ---------------- 3xTF32 GEMM body: C[128,128 tile] = A * W -------------------
// 256 threads (8 warps), 128x128 output tile, K-chunks of 32.
__device__ __forceinline__ void gemm_body(
    float (*As)[36], float (*Bs)[136],
    const float* __restrict__ A, const float* __restrict__ W,
    float* __restrict__ C, int n, int m0) {
    int tid = threadIdx.x;
    int lane = tid & 31, wid = tid >> 5;
    int wm = wid >> 1;
    int wn = wid & 1;

    float acc[2][8][4];
    #pragma unroll
    for (int ms = 0; ms < 2; ms++)
        #pragma unroll
        for (int nt = 0; nt < 8; nt++)
            #pragma unroll
            for (int j = 0; j < 4; j++) acc[ms][nt][j] = 0.0f;

    int kq = lane & 3;
    int rq = lane >> 2;

    for (int k0 = 0; k0 < 128; k0 += 32) {
        #pragma unroll
        for (int it = 0; it < 4; it++) {
            int f = tid + 256 * it;
            int row = f >> 3;
            int k4 = (f & 7) * 4;
            int rg = m0 + row;
            if (rg >= n) rg = n - 1;
            float4 a = *(const float4*)&A[(size_t)rg * 128 + k0 + k4];
            *(float4*)&As[row][k4] = a;
        }
        #pragma unroll
        for (int it = 0; it < 4; it++) {
            int f = tid + 256 * it;
            int k = f >> 5;
            int nc = (f & 31) * 4;
            float4 b = *(const float4*)&W[(size_t)(k0 + k) * 128 + nc];
            *(float4*)&Bs[k][nc] = b;
        }
        __syncthreads();

        #pragma unroll
        for (int kk = 0; kk < 32; kk += 8) {
            #pragma unroll
            for (int ms = 0; ms < 2; ms++) {
                int r = wm * 32 + ms * 16 + rq;
                float af0 = As[r][kk + kq];
                float af1 = As[r + 8][kk + kq];
                float af2 = As[r][kk + kq + 4];
                float af3 = As[r + 8][kk + kq + 4];
                uint32_t ah0 = f2tf32(af0), ah1 = f2tf32(af1);
                uint32_t ah2 = f2tf32(af2), ah3 = f2tf32(af3);
                uint32_t al0 = f2tf32(af0 - __uint_as_float(ah0));
                uint32_t al1 = f2tf32(af1 - __uint_as_float(ah1));
                uint32_t al2 = f2tf32(af2 - __uint_as_float(ah2));
                uint32_t al3 = f2tf32(af3 - __uint_as_float(ah3));
                #pragma unroll
                for (int nt = 0; nt < 8; nt++) {
                    int nc = wn * 64 + nt * 8 + rq;
                    float bf0 = Bs[kk + kq][nc];
                    float bf1 = Bs[kk + kq + 4][nc];
                    uint32_t bh0 = f2tf32(bf0), bh1 = f2tf32(bf1);
                    uint32_t bl0 = f2tf32(bf0 - __uint_as_float(bh0));
                    uint32_t bl1 = f2tf32(bf1 - __uint_as_float(bh1));
                    mma_tf32(acc[ms][nt], al0, al1, al2, al3, bh0, bh1);
                    mma_tf32(acc[ms][nt], ah0, ah1, ah2, ah3, bl0, bl1);
                    mma_tf32(acc[ms][nt], ah0, ah1, ah2, ah3, bh0, bh1);
                }
            }
        }
        __syncthreads();
    }

    #pragma unroll
    for (int ms = 0; ms < 2; ms++) {
        int r0 = m0 + wm * 32 + ms * 16 + rq;
        #pragma unroll
        for (int nt = 0; nt < 8; nt++) {
            int nc = wn * 64 + nt * 8 + (lane & 3) * 2;
            if (r0 < n) {
                float2 v = {acc[ms][nt][0], acc[ms][nt][1]};
                *(float2*)&C[(size_t)r0 * 128 + nc] = v;
            }
            if (r0 + 8 < n) {
                float2 v = {acc[ms][nt][2], acc[ms][nt][3]};
                *(float2*)&C[(size_t)(r0 + 8) * 128 + nc] = v;
            }
        }
    }
}

// ---------------- fused: count | pool-zero | GEMM0 ----------------------------
__global__ void __launch_bounds__(256) fusedA_kernel(
    const int* __restrict__ dst, int e,
    float* __restrict__ pool, int gsize,
    const float* __restrict__ A, const float* __restrict__ W,
    float* __restrict__ C, int n, int count_blocks, int zero_blocks) {
    __shared__ float As[128][36];
    __shared__ float Bs[32][136];
    int b = blockIdx.x;
    if (b < count_blocks) {
        int i = b * 256 + threadIdx.x;
        if (i < e) atomicAdd(&g_cnt[dst[i]], 1);
    } else if (b < count_blocks + zero_blocks) {
        int i = (b - count_blocks) * 256 + threadIdx.x;
        if (i < gsize) pool[i] = 0.0f;
    } else {
        gemm_body(As, Bs, A, W, C, n, (b - count_blocks - zero_blocks) * 128);
    }
}

// ---------------- plain GEMM kernel (layer 1) ----------------------------------
__global__ void __launch_bounds__(256) gemm_tf32_kernel(
    const float* __restrict__ A, const float* __restrict__ W,
    float* __restrict__ C, int n) {
    __shared__ float As[128][36];
    __shared__ float Bs[32][136];
    gemm_body(As, Bs, A, W, C, n, blockIdx.x * 128);
}

// ---------------- scan phase 1: per-chunk reduce ------------------------------
__global__ void __launch_bounds__(256) reduce_kernel(int n) {
    __shared__ int ws[8];
    int b = blockIdx.x, tid = threadIdx.x;
    int lane = tid & 31, wid = tid >> 5;
    int i = b * SCHUNK + tid * 2;
    int s = (i < n ? g_cnt[i] : 0) + (i + 1 < n ? g_cnt[i + 1] : 0);
    #pragma unroll
    for (int d = 16; d > 0; d >>= 1) s += __shfl_down_sync(0xFFFFFFFFu, s, d);
    if (lane == 0) ws[wid] = s;
    __syncthreads();
    if (tid == 0) {
        int t = 0;
        #pragma unroll
        for (int w = 0; w < 8; w++) t += ws[w];
        g_bsum[b] = t;
    }
}

// ---------------- scan phase 2: scan the chunk sums (1 block) -----------------
__global__ void scan_bsums_kernel(int nb) {
    __shared__ int ws[4];
    int tid = threadIdx.x;              // 128 threads
    int lane = tid & 31, wid = tid >> 5;
    int v = tid < nb ? g_bsum[tid] : 0;
    int x = v;
    #pragma unroll
    for (int d = 1; d < 32; d <<= 1) {
        int y = __shfl_up_sync(0xFFFFFFFFu, x, d);
        if (lane >= d) x += y;
    }
    if (lane == 31) ws[wid] = x;
    __syncthreads();
    int add = 0;
    for (int w = 0; w < wid; w++) add += ws[w];
    if (tid < nb) g_boff[tid] = x - v + add;
}

// ---------------- scan phase 3: per-chunk scan + write rowptr/dinv/cur --------
__global__ void __launch_bounds__(256) scan_write_kernel(int n) {
    __shared__ int ws[8];
    int b = blockIdx.x, tid = threadIdx.x;
    int lane = tid & 31, wid = tid >> 5;
    int base = b * SCHUNK + tid * 2;
    int v0 = base < n ? g_cnt[base] : 0;
    int v1 = base + 1 < n ? g_cnt[base + 1] : 0;
    int t = v0 + v1;
    int x = t;
    #pragma unroll
    for (int d = 1; d < 32; d <<= 1) {
        int y = __shfl_up_sync(0xFFFFFFFFu, x, d);
        if (lane >= d) x += y;
    }
    if (lane == 31) ws[wid] = x;
    __syncthreads();
    int add = g_boff[b];
    for (int w = 0; w < wid; w++) add += ws[w];
    int excl = x - t + add;
    if (base < n) {
        g_rowptr[base + 1] = excl + v0;
        g_cur[base] = excl;
        g_dinv[base] = rsqrtf((float)(v0 + 1));  // +1 self loop
        g_cnt[base] = 0;                         // restore invariant
    }
    if (base + 1 < n) {
        g_rowptr[base + 2] = excl + v0 + v1;
        g_cur[base + 1] = excl + v0;
        g_dinv[base + 1] = rsqrtf((float)(v1 + 1));
        g_cnt[base + 1] = 0;
    }
    if (b == 0 && tid == 0) g_rowptr[0] = 0;
}

// ---------------- CSR fill ----------------------------------------------------
__global__ void fill_kernel(const int* __restrict__ src,
                            const int* __restrict__ dst, int e) {
    int i = blockIdx.x * blockDim.x + threadIdx.x;
    if (i < e) {
        int pos = atomicAdd(&g_cur[dst[i]], 1);
        g_col[pos] = src[i];
    }
}

// ---------------- gather + bias + PReLU + pooled reduction --------------------
// 8 warps/block = 8 nodes/block. batch is sorted -> blocks are almost always
// single-graph; reduce in smem and emit 128 global atomics instead of 1024.
__global__ void __launch_bounds__(256) gather_kernel(
    const float* __restrict__ zw,
    const float* __restrict__ bias,
    const float* __restrict__ alpha,
    const int* __restrict__ batch,
    float* __restrict__ zout,
    float* __restrict__ pool,
    int n) {
    __shared__ float sred[8][132];
    __shared__ int sgi[8];
    int wid = threadIdx.x >> 5, lane = threadIdx.x & 31;
    int i = blockIdx.x * 8 + wid;
    bool valid = i < n;

    float z0 = 0.f, z1 = 0.f, z2 = 0.f, z3 = 0.f;
    int gi = -1;

    if (valid) {
        const float4* __restrict__ zwv = (const float4*)zw;
        float di = g_dinv[i];
        float4 v = zwv[(size_t)i * 32 + lane];
        float4 acc;
        acc.x = di * v.x; acc.y = di * v.y; acc.z = di * v.z; acc.w = di * v.w;

        int e0 = g_rowptr[i], e1 = g_rowptr[i + 1];
        int e = e0;
        for (; e + 4 <= e1; e += 4) {
            int s0 = g_col[e + 0];
            int s1 = g_col[e + 1];
            int s2 = g_col[e + 2];
            int s3 = g_col[e + 3];
            float4 u0 = zwv[(size_t)s0 * 32 + lane];
            float4 u1 = zwv[(size_t)s1 * 32 + lane];
            float4 u2 = zwv[(size_t)s2 * 32 + lane];
            float4 u3 = zwv[(size_t)s3 * 32 + lane];
            float d0 = g_dinv[s0], d1 = g_dinv[s1];
            float d2 = g_dinv[s2], d3 = g_dinv[s3];
            acc.x = fmaf(d0, u0.x, fmaf(d1, u1.x, fmaf(d2, u2.x, fmaf(d3, u3.x, acc.x))));
            acc.y = fmaf(d0, u0.y, fmaf(d1, u1.y, fmaf(d2, u2.y, fmaf(d3, u3.y, acc.y))));
            acc.z = fmaf(d0, u0.z, fmaf(d1, u1.z, fmaf(d2, u2.z, fmaf(d3, u3.z, acc.z))));
            acc.w = fmaf(d0, u0.w, fmaf(d1, u1.w, fmaf(d2, u2.w, fmaf(d3, u3.w, acc.w))));
        }
        for (; e < e1; e++) {
            int s = g_col[e];
            float ds = g_dinv[s];
            float4 u = zwv[(size_t)s * 32 + lane];
            acc.x = fmaf(ds, u.x, acc.x);
            acc.y = fmaf(ds, u.y, acc.y);
            acc.z = fmaf(ds, u.z, acc.z);
            acc.w = fmaf(ds, u.w, acc.w);
        }

        float4 b  = ((const float4*)bias)[lane];
        float4 al = ((const float4*)alpha)[lane];
        z0 = fmaf(acc.x, di, b.x);
        z1 = fmaf(acc.y, di, b.y);
        z2 = fmaf(acc.z, di, b.z);
        z3 = fmaf(acc.w, di, b.w);
        z0 = z0 > 0.0f ? z0 : al.x * z0;
        z1 = z1 > 0.0f ? z1 : al.y * z1;
        z2 = z2 > 0.0f ? z2 : al.z * z2;
        z3 = z3 > 0.0f ? z3 : al.w * z3;

        float4 out = {z0, z1, z2, z3};
        ((float4*)zout)[(size_t)i * 32 + lane] = out;
        gi = batch[i];
    }

    if (lane == 0) sgi[wid] = gi;
    sred[wid][lane * 4 + 0] = z0;
    sred[wid][lane * 4 + 1] = z1;
    sred[wid][lane * 4 + 2] = z2;
    sred[wid][lane * 4 + 3] = z3;
    __syncthreads();

    int g0 = sgi[0];
    bool uni = (g0 >= 0);
    #pragma unroll
    for (int w = 1; w < 8; w++) uni = uni && (sgi[w] == g0);

    if (uni) {
        int f = threadIdx.x;
        if (f < 128) {
            float s = 0.f;
            #pragma unroll
            for (int w = 0; w < 8; w++) s += sred[w][f];
            atomicAdd(&pool[(size_t)g0 * 256 + f], s);
        }
    } else if (valid) {
        float* p = &pool[(size_t)gi * 256 + lane * 4];
        atomicAdd(p + 0, z0);
        atomicAdd(p + 1, z1);
        atomicAdd(p + 2, z2);
        atomicAdd(p + 3, z3);
    }
}

// ---------------- launch -------------------------------------------------------
extern "C" void kernel_launch(void* const* d_in, const int* in_sizes, int n_in,
                              void* d_out, int out_size) {
    const float* x      = (const float*)d_in[0];
    const int*   eidx   = (const int*)d_in[1];
    const int*   batch  = (const int*)d_in[2];
    const float* W0     = (const float*)d_in[3];
    const float* b0     = (const float*)d_in[4];
    const float* alpha0 = (const float*)d_in[5];
    const float* W1     = (const float*)d_in[6];
    const float* b1     = (const float*)d_in[7];
    const float* alpha1 = (const float*)d_in[8];

    int n = in_sizes[0] / HH;       // 50000
    int e = in_sizes[1] / 2;        // 800000
    const int* src = eidx;
    const int* dst = eidx + e;

    float* z2_out = (float*)d_out;                   // [n,128]
    float* g_pool = (float*)d_out + (size_t)n * HH;  // [G, 256]
    int gsize = out_size - n * HH;                   // 65536

    float* zw;  cudaGetSymbolAddress((void**)&zw, g_zw);
    float* z1;  cudaGetSymbolAddress((void**)&z1, g_z1);

    int nb = (n + SCHUNK - 1) / SCHUNK;
    int count_blocks = (e + 255) / 256;
    int zero_blocks  = (gsize + 255) / 256;
    int gemm_blocks  = (n + 127) / 128;
    int gather_blocks = (n + 7) / 8;

    // Phase A: count degrees + zero pool + GEMM layer 0 (all independent)
    fusedA_kernel<<<count_blocks + zero_blocks + gemm_blocks, 256>>>(
        dst, e, g_pool, gsize, x, W0, zw, n, count_blocks, zero_blocks);

    // CSR build
    reduce_kernel<<<nb, 256>>>(n);
    scan_bsums_kernel<<<1, 128>>>(nb);
    scan_write_kernel<<<nb, 256>>>(n);
    fill_kernel<<<count_blocks, 256>>>(src, dst, e);

    // Layer 0 aggregate
    gather_kernel<<<gather_blocks, 256>>>(zw, b0, alpha0, batch, z1, g_pool, n);
    // Layer 1
    gemm_tf32_kernel<<<gemm_blocks, 256>>>(z1, W1, zw, n);
    gather_kernel<<<gather_blocks, 256>>>(zw, b1, alpha1, batch, z2_out,
                                          g_pool + HH, n);
}